// round 8
// baseline (speedup 1.0000x reference)
#include <cuda_runtime.h>

#define NN 100000
#define NE 1250000
#define D  64
#define NB 16
#define SCAN_B 391          // virtual scan blocks of 256 nodes
#define TM 32               // nodes per transform tile (100000 % 32 == 0 via 3125 tiles)
#define NTILE (NN / TM)     // 3125
#define IN_STRIDE 132       // 128 + 4 pad

// Scratch (no allocs). Invariant: g_cnt is ZERO at entry of every launch
// (zero at module load; phase 3 re-zeroes it each launch).
__device__ float    g_h[(size_t)NN * D];
__device__ int      g_cnt[NN];
__device__ int      g_off[NN + 1];
__device__ int      g_pos[NN];
__device__ int      g_blk[512];
__device__ int      g_srcs[NE];
__device__ float    g_Wm[D * D];
__device__ float    g_Ws[D * D];
__device__ float    g_bm[D];
__device__ float    g_bs[D];
__device__ unsigned g_bar;   // monotonic barrier counter (persists across replays)

__device__ __forceinline__ void grid_barrier(unsigned nblk) {
    __syncthreads();
    if (threadIdx.x == 0) {
        __threadfence();
        unsigned old = atomicAdd(&g_bar, 1u);
        unsigned target = (old / nblk + 1u) * nblk;
        unsigned v;
        do {
            asm volatile("ld.acquire.gpu.global.u32 %0, [%1];" : "=r"(v) : "l"(&g_bar));
        } while (v < target);
    }
    __syncthreads();
}

// Shared layout (52 KB): In[TM*IN_STRIDE] | W[128*64] | red[TM*17] | nf[TM]
// Scan phases reuse the first 2 KB as int[512].
#define SMEM_FLOATS (TM * IN_STRIDE + 128 * D + TM * 17 + TM)
#define SMEM_BYTES  (SMEM_FLOATS * (int)sizeof(float))

__global__ void __launch_bounds__(256, 4)
k_fused(const float*  __restrict__ x,
        const int*    __restrict__ ei,
        const float*  __restrict__ bmw, const float* __restrict__ bmb,
        const float*  __restrict__ bsw, const float* __restrict__ bsb,
        const float*  __restrict__ lc,
        float* __restrict__ out) {
    extern __shared__ float smem[];
    int* si = (int*)smem;
    const int tid  = threadIdx.x;
    const unsigned grid = gridDim.x;

    // ---------------- Phase 0: weights (block 0) + dst histogram ----------
    if (blockIdx.x == 0) {
        __shared__ float c[NB];
        if (tid < NB) c[tid] = lc[tid];
        __syncthreads();
        for (int idx = tid; idx < D * D; idx += 256) {
            float wm = 0.f, ws = 0.f;
            #pragma unroll
            for (int b = 0; b < NB; b++) {
                wm = fmaf(bmw[idx * NB + b], c[b], wm);
                ws = fmaf(bsw[idx * NB + b], c[b], ws);
            }
            g_Wm[idx] = wm;
            g_Ws[idx] = ws;
        }
        if (tid < D) {
            float bm = 0.f, bs = 0.f;
            #pragma unroll
            for (int b = 0; b < NB; b++) {
                bm = fmaf(bmb[tid * NB + b], c[b], bm);
                bs = fmaf(bsb[tid * NB + b], c[b], bs);
            }
            g_bm[tid] = bm;
            g_bs[tid] = bs;
        }
    }
    for (unsigned e = blockIdx.x * 256u + tid; e < NE; e += grid * 256u)
        atomicAdd(&g_cnt[__ldg(ei + NE + e)], 1);

    grid_barrier(grid);

    // ---------------- Phase 1: per-chunk scan of g_cnt -> g_off -----------
    for (unsigned vb = blockIdx.x; vb < SCAN_B; vb += grid) {
        int i = vb * 256 + tid;
        int v = (i < NN) ? g_cnt[i] : 0;
        si[tid] = v;
        __syncthreads();
        #pragma unroll
        for (int d = 1; d < 256; d <<= 1) {
            int u = (tid >= d) ? si[tid - d] : 0;
            __syncthreads();
            si[tid] += u;
            __syncthreads();
        }
        if (i < NN) g_off[i] = si[tid] - v;
        if (tid == 255) g_blk[vb] = si[255];
        __syncthreads();
    }

    grid_barrier(grid);

    // ---------------- Phase 2: scan block totals (block 0 only) -----------
    if (blockIdx.x == 0) {
        int v0 = (tid < SCAN_B) ? g_blk[tid] : 0;
        int v1 = (tid + 256 < SCAN_B) ? g_blk[tid + 256] : 0;
        si[tid] = v0;
        si[tid + 256] = v1;
        __syncthreads();
        #pragma unroll
        for (int d = 1; d < 512; d <<= 1) {
            int u0 = (tid >= d) ? si[tid - d] : 0;
            int u1 = (tid + 256 >= d) ? si[tid + 256 - d] : 0;
            __syncthreads();
            si[tid] += u0;
            si[tid + 256] += u1;
            __syncthreads();
        }
        if (tid < SCAN_B) g_blk[tid] = si[tid] - v0;
        if (tid + 256 < SCAN_B) g_blk[tid + 256] = si[tid + 256] - v1;
    }

    grid_barrier(grid);

    // ---------------- Phase 3: finalize offsets, init pos, clean cnt ------
    for (unsigned vb = blockIdx.x; vb < SCAN_B; vb += grid) {
        int i = vb * 256 + tid;
        if (i < NN) {
            int o = g_off[i] + g_blk[vb];
            g_off[i] = o;
            g_pos[i] = o;
            g_cnt[i] = 0;                    // self-clean for next launch
        }
    }
    if (blockIdx.x == 0 && tid == 0) g_off[NN] = NE;

    grid_barrier(grid);

    // ---------------- Phase 4: counting-sort fill of src list -------------
    for (unsigned e = blockIdx.x * 256u + tid; e < NE; e += grid * 256u) {
        int d = __ldg(ei + NE + e);
        int p = atomicAdd(&g_pos[d], 1);
        g_srcs[p] = __ldg(ei + e);
    }

    grid_barrier(grid);

    // ---------------- Phase 5: atomic-free aggregation (warp per node) ----
    {
        const float2* x2 = (const float2*)x;
        int l = tid & 31;
        int nwarp = grid * 8;
        for (int n = blockIdx.x * 8 + (tid >> 5); n < NN; n += nwarp) {
            int start = __ldg(&g_off[n]);
            int end   = __ldg(&g_off[n + 1]);
            float2 acc = make_float2(0.f, 0.f);
            int e = start;
            for (; e + 4 <= end; e += 4) {
                int s0 = __ldg(g_srcs + e);
                int s1 = __ldg(g_srcs + e + 1);
                int s2 = __ldg(g_srcs + e + 2);
                int s3 = __ldg(g_srcs + e + 3);
                float2 v0 = __ldg(x2 + (size_t)s0 * 32 + l);
                float2 v1 = __ldg(x2 + (size_t)s1 * 32 + l);
                float2 v2 = __ldg(x2 + (size_t)s2 * 32 + l);
                float2 v3 = __ldg(x2 + (size_t)s3 * 32 + l);
                acc.x += v0.x + v1.x + v2.x + v3.x;
                acc.y += v0.y + v1.y + v2.y + v3.y;
            }
            for (; e < end; e++) {
                int s0 = __ldg(g_srcs + e);
                float2 v0 = __ldg(x2 + (size_t)s0 * 32 + l);
                acc.x += v0.x;
                acc.y += v0.y;
            }
            ((float2*)g_h)[(size_t)n * 32 + l] = acc;
        }
    }

    grid_barrier(grid);

    // ---------------- Phase 6: transform + L2 normalize -------------------
    {
        float* In  = smem;                     // [TM][IN_STRIDE]
        float* Wsh = In + TM * IN_STRIDE;      // [128][64] flat
        float* red = Wsh + 128 * D;            // [TM][17]
        float* nf  = red + TM * 17;            // [TM]

        // Load W once (persists across tiles)
        {
            const float4* wm4 = (const float4*)g_Wm;
            const float4* ws4 = (const float4*)g_Ws;
            float4* w4 = (float4*)Wsh;
            for (int i = tid; i < (D * D) / 4; i += 256) {
                w4[i] = wm4[i];
                w4[i + (D * D) / 4] = ws4[i];
            }
        }
        int to = tid & 15;          // col group
        int tn = tid >> 4;          // row group (2 rows each: tn*2, tn*2+1)

        float bmv[4], bsv[4];
        #pragma unroll
        for (int c = 0; c < 4; c++) {
            bmv[c] = g_bm[to * 4 + c];
            bsv[c] = g_bs[to * 4 + c];
        }
        __syncthreads();

        const float4* h4 = (const float4*)g_h;
        const float4* x4 = (const float4*)x;

        for (int tile = blockIdx.x; tile < NTILE; tile += grid) {
            int n0 = tile * TM;
            // load In: rows = 32 nodes, cols 0:64 h | 64:128 x
            for (int i = tid; i < TM * (D / 4); i += 256) {
                int n = i >> 4, j = i & 15;
                size_t off = (size_t)(n0 + n) * (D / 4) + j;
                *(float4*)&In[n * IN_STRIDE + j * 4]      = h4[off];
                *(float4*)&In[n * IN_STRIDE + 64 + j * 4] = x4[off];
            }
            __syncthreads();

            float acc[2][4];
            #pragma unroll
            for (int r = 0; r < 2; r++)
                #pragma unroll
                for (int c = 0; c < 4; c++) acc[r][c] = 0.f;

            const float* a0 = &In[(tn * 2 + 0) * IN_STRIDE];
            const float* a1 = &In[(tn * 2 + 1) * IN_STRIDE];

            #pragma unroll 8
            for (int k = 0; k < 128; k++) {
                float4 b = *(const float4*)&Wsh[k * D + to * 4];
                float v0 = a0[k], v1 = a1[k];
                acc[0][0] = fmaf(v0, b.x, acc[0][0]);
                acc[0][1] = fmaf(v0, b.y, acc[0][1]);
                acc[0][2] = fmaf(v0, b.z, acc[0][2]);
                acc[0][3] = fmaf(v0, b.w, acc[0][3]);
                acc[1][0] = fmaf(v1, b.x, acc[1][0]);
                acc[1][1] = fmaf(v1, b.y, acc[1][1]);
                acc[1][2] = fmaf(v1, b.z, acc[1][2]);
                acc[1][3] = fmaf(v1, b.w, acc[1][3]);
            }

            float vals[2][4];
            #pragma unroll
            for (int r = 0; r < 2; r++) {
                int gn = n0 + tn * 2 + r;
                float dg = (float)(__ldg(&g_off[gn + 1]) - __ldg(&g_off[gn]));
                float ss = 0.f;
                #pragma unroll
                for (int c = 0; c < 4; c++) {
                    float v = acc[r][c] + dg * bmv[c] + bsv[c];
                    vals[r][c] = v;
                    ss = fmaf(v, v, ss);
                }
                red[(tn * 2 + r) * 17 + to] = ss;
            }
            __syncthreads();

            if (tid < TM) {
                float s = 0.f;
                #pragma unroll
                for (int t2 = 0; t2 < 16; t2++) s += red[tid * 17 + t2];
                nf[tid] = 1.f / fmaxf(sqrtf(s), 1e-12f);
            }
            __syncthreads();

            #pragma unroll
            for (int r = 0; r < 2; r++) {
                int n = tn * 2 + r;
                float f = nf[n];
                *(float4*)&out[(size_t)(n0 + n) * D + to * 4] =
                    make_float4(vals[r][0] * f, vals[r][1] * f,
                                vals[r][2] * f, vals[r][3] * f);
            }
            __syncthreads();   // before next tile overwrites In/red/nf
        }
    }
}

extern "C" void kernel_launch(void* const* d_in, const int* in_sizes, int n_in,
                              void* d_out, int out_size) {
    const float* x   = (const float*)d_in[0];
    const int*   ei  = (const int*)d_in[1];
    const float* bmw = (const float*)d_in[2];
    const float* bmb = (const float*)d_in[3];
    const float* bsw = (const float*)d_in[4];
    const float* bsb = (const float*)d_in[5];
    const float* lc  = (const float*)d_in[6];
    float* out = (float*)d_out;

    cudaFuncSetAttribute(k_fused, cudaFuncAttributeMaxDynamicSharedMemorySize, SMEM_BYTES);

    int dev = 0;
    cudaGetDevice(&dev);
    int sms = 0;
    cudaDeviceGetAttribute(&sms, cudaDevAttrMultiProcessorCount, dev);
    int occ = 0;
    cudaOccupancyMaxActiveBlocksPerMultiprocessor(&occ, k_fused, 256, SMEM_BYTES);
    if (occ < 1) occ = 1;
    unsigned grid = (unsigned)(sms * occ);   // all blocks resident -> barrier safe

    k_fused<<<grid, 256, SMEM_BYTES>>>(x, ei, bmw, bmb, bsw, bsb, lc, out);
}

// round 10
// speedup vs baseline: 1.2210x; 1.2210x over previous
#include <cuda_runtime.h>

#define NN 100000
#define NE 1250000
#define D  64
#define NB 16

// Scratch (no allocs) — g_h/g_deg zeroed every launch via cudaMemsetAsync.
__device__ float g_h[(size_t)NN * D];   // sum of x[src] per dst node
__device__ float g_deg[NN];             // in-degree (float)
__device__ float g_WH[128 * D];         // concat W (k=0..63 Wm, 64..127 Ws), TF32-hi plane
__device__ float g_WL[128 * D];         // TF32-lo plane
__device__ float g_bm[D];
__device__ float g_bs[D];

__device__ __forceinline__ unsigned f2tf(float v) {
    unsigned r;
    asm("cvt.rna.tf32.f32 %0, %1;" : "=r"(r) : "f"(v));
    return r;
}

// ---------------------------------------------------------------------------
// Kernel 1: scatter-add raw x rows (16 threads/edge, float4 vector atomics).
// Block 0 reconstructs W from bases AND precomputes the TF32 hi/lo planes
// (hidden under the ~90us scatter).
// ---------------------------------------------------------------------------
__global__ void k_scatter(const float4* __restrict__ x4, const int* __restrict__ ei,
                          const float* __restrict__ bmw, const float* __restrict__ bmb,
                          const float* __restrict__ bsw, const float* __restrict__ bsb,
                          const float* __restrict__ lc) {
    if (blockIdx.x == 0) {
        __shared__ float c[NB];
        if (threadIdx.x < NB) c[threadIdx.x] = lc[threadIdx.x];
        __syncthreads();
        for (int idx = threadIdx.x; idx < D * D; idx += 256) {
            int i = idx >> 6, o = idx & 63;
            float wm = 0.f, ws = 0.f;
            #pragma unroll
            for (int b = 0; b < NB; b++) {
                wm = fmaf(bmw[idx * NB + b], c[b], wm);
                ws = fmaf(bsw[idx * NB + b], c[b], ws);
            }
            float wmH = __uint_as_float(f2tf(wm));
            float wsH = __uint_as_float(f2tf(ws));
            g_WH[i * D + o]        = wmH;
            g_WL[i * D + o]        = __uint_as_float(f2tf(wm - wmH));
            g_WH[(64 + i) * D + o] = wsH;
            g_WL[(64 + i) * D + o] = __uint_as_float(f2tf(ws - wsH));
        }
        if (threadIdx.x < D) {
            int o = threadIdx.x;
            float bm = 0.f, bs = 0.f;
            #pragma unroll
            for (int b = 0; b < NB; b++) {
                bm = fmaf(bmb[o * NB + b], c[b], bm);
                bs = fmaf(bsb[o * NB + b], c[b], bs);
            }
            g_bm[o] = bm;
            g_bs[o] = bs;
        }
        return;
    }
    unsigned t = (blockIdx.x - 1) * blockDim.x + threadIdx.x;
    unsigned e = t >> 4;
    if (e >= NE) return;
    int j = t & 15;
    int src = __ldg(ei + e);
    int dst = __ldg(ei + NE + e);
    float4 v = __ldg(x4 + (size_t)src * (D / 4) + j);
    float* p = g_h + (size_t)dst * D + j * 4;
    asm volatile("red.global.add.v4.f32 [%0], {%1,%2,%3,%4};"
                 :: "l"(p), "f"(v.x), "f"(v.y), "f"(v.z), "f"(v.w)
                 : "memory");
    if (j == 0) atomicAdd(&g_deg[dst], 1.0f);
}

// ---------------------------------------------------------------------------
// Kernel 2: out = normalize( h @ Wm + x @ Ws + deg*bm + bs )
// Tensor cores, 3xTF32.  W hi/lo planes precomputed (no per-tile weight cvt);
// A split on the fly.  Block = 64 nodes x 64 cols, 128 threads / 4 warps,
// each warp 16 rows x 64 cols, K = 128 (concat [h|x]).
// ---------------------------------------------------------------------------
#define IN_STRIDE 132   // 128 + 4 pad (A loads conflict-free)
#define W_STRIDE  72    // 64 + 8 pad  (B loads: banks 72t+g -> 32 distinct)

#define MMA_TF32(c0,c1,c2,c3, a0,a1,a2,a3, b0,b1)                               \
    asm volatile("mma.sync.aligned.m16n8k8.row.col.f32.tf32.tf32.f32 "          \
                 "{%0,%1,%2,%3}, {%4,%5,%6,%7}, {%8,%9}, {%0,%1,%2,%3};"        \
                 : "+f"(c0), "+f"(c1), "+f"(c2), "+f"(c3)                       \
                 : "r"(a0), "r"(a1), "r"(a2), "r"(a3), "r"(b0), "r"(b1))

__global__ void __launch_bounds__(128, 2)
k_transform(const float* __restrict__ x, float* __restrict__ out) {
    extern __shared__ float smem[];
    float* In   = smem;                     // [64][IN_STRIDE]  concat(h|x)
    float* WHs  = In + 64 * IN_STRIDE;      // [128][W_STRIDE]  hi plane
    float* WLs  = WHs + 128 * W_STRIDE;     // [128][W_STRIDE]  lo plane
    float* degS = WLs + 128 * W_STRIDE;     // [64]
    float* bmS  = degS + 64;                // [64]
    float* bsS  = bmS + 64;                 // [64]

    int tid  = threadIdx.x;
    int w    = tid >> 5;        // warp 0..3 -> rows w*16 .. w*16+15
    int lane = tid & 31;
    int g    = lane >> 2;       // 0..7
    int t    = lane & 3;        // 0..3
    int n0   = blockIdx.x * 64;

    // --- Prologue: stage W planes and inputs into shared ---
    {
        const float4* wh4 = (const float4*)g_WH;
        const float4* wl4 = (const float4*)g_WL;
        for (int i = tid; i < (128 * D) / 4; i += 128) {
            int r = i >> 4, c = i & 15;
            *(float4*)&WHs[r * W_STRIDE + c * 4] = wh4[i];
            *(float4*)&WLs[r * W_STRIDE + c * 4] = wl4[i];
        }
    }
    {
        const float4* h4 = (const float4*)g_h;
        const float4* x4 = (const float4*)x;
        for (int i = tid; i < 64 * (D / 4); i += 128) {
            int n = i >> 4, j = i & 15;
            int gn = n0 + n;
            float4 hv = make_float4(0.f, 0.f, 0.f, 0.f);
            float4 xv = hv;
            if (gn < NN) {
                size_t off = (size_t)gn * (D / 4) + j;
                hv = h4[off];
                xv = x4[off];
            }
            *(float4*)&In[n * IN_STRIDE + j * 4]      = hv;
            *(float4*)&In[n * IN_STRIDE + 64 + j * 4] = xv;
        }
    }
    if (tid < 64) {
        int gn = n0 + tid;
        degS[tid] = (gn < NN) ? g_deg[gn] : 0.f;
        bmS[tid]  = g_bm[tid];
        bsS[tid]  = g_bs[tid];
    }
    __syncthreads();

    // --- Main loop: 16 k-chunks of 8, 8 n-tiles, 3 MMAs per tile ---
    float acc[8][4];
    #pragma unroll
    for (int tl = 0; tl < 8; tl++)
        #pragma unroll
        for (int j = 0; j < 4; j++) acc[tl][j] = 0.f;

    const int rowA = w * 16 + g;
    const float* aRow0 = &In[rowA * IN_STRIDE];
    const float* aRow1 = &In[(rowA + 8) * IN_STRIDE];

    #pragma unroll 4
    for (int kc = 0; kc < 16; kc++) {
        int kb = kc * 8;
        // A fragment (rows g, g+8; cols t, t+4) with on-the-fly hi/lo split
        float fa0 = aRow0[kb + t];
        float fa1 = aRow1[kb + t];
        float fa2 = aRow0[kb + t + 4];
        float fa3 = aRow1[kb + t + 4];
        unsigned aH0 = f2tf(fa0), aH1 = f2tf(fa1), aH2 = f2tf(fa2), aH3 = f2tf(fa3);
        unsigned aL0 = f2tf(fa0 - __uint_as_float(aH0));
        unsigned aL1 = f2tf(fa1 - __uint_as_float(aH1));
        unsigned aL2 = f2tf(fa2 - __uint_as_float(aH2));
        unsigned aL3 = f2tf(fa3 - __uint_as_float(aH3));

        const float* whb0 = &WHs[(kb + t) * W_STRIDE + g];
        const float* whb1 = &WHs[(kb + t + 4) * W_STRIDE + g];
        const float* wlb0 = &WLs[(kb + t) * W_STRIDE + g];
        const float* wlb1 = &WLs[(kb + t + 4) * W_STRIDE + g];
        #pragma unroll
        for (int tl = 0; tl < 8; tl++) {
            unsigned bH0 = __float_as_uint(whb0[tl * 8]);
            unsigned bH1 = __float_as_uint(whb1[tl * 8]);
            unsigned bL0 = __float_as_uint(wlb0[tl * 8]);
            unsigned bL1 = __float_as_uint(wlb1[tl * 8]);
            MMA_TF32(acc[tl][0], acc[tl][1], acc[tl][2], acc[tl][3],
                     aH0, aH1, aH2, aH3, bH0, bH1);
            MMA_TF32(acc[tl][0], acc[tl][1], acc[tl][2], acc[tl][3],
                     aH0, aH1, aH2, aH3, bL0, bL1);
            MMA_TF32(acc[tl][0], acc[tl][1], acc[tl][2], acc[tl][3],
                     aL0, aL1, aL2, aL3, bH0, bH1);
        }
    }

    // --- Epilogue: bias + deg*bm, L2 norm across quad lanes, store ---
    float dg0 = degS[rowA];
    float dg1 = degS[rowA + 8];
    float ss0 = 0.f, ss1 = 0.f;
    #pragma unroll
    for (int tl = 0; tl < 8; tl++) {
        int c0 = tl * 8 + 2 * t;
        float bm0 = bmS[c0], bm1 = bmS[c0 + 1];
        float bs0 = bsS[c0], bs1 = bsS[c0 + 1];
        float v00 = acc[tl][0] + dg0 * bm0 + bs0;
        float v01 = acc[tl][1] + dg0 * bm1 + bs1;
        float v10 = acc[tl][2] + dg1 * bm0 + bs0;
        float v11 = acc[tl][3] + dg1 * bm1 + bs1;
        acc[tl][0] = v00; acc[tl][1] = v01; acc[tl][2] = v10; acc[tl][3] = v11;
        ss0 = fmaf(v00, v00, fmaf(v01, v01, ss0));
        ss1 = fmaf(v10, v10, fmaf(v11, v11, ss1));
    }
    ss0 += __shfl_xor_sync(0xffffffffu, ss0, 1);
    ss0 += __shfl_xor_sync(0xffffffffu, ss0, 2);
    ss1 += __shfl_xor_sync(0xffffffffu, ss1, 1);
    ss1 += __shfl_xor_sync(0xffffffffu, ss1, 2);
    float f0 = 1.f / fmaxf(sqrtf(ss0), 1e-12f);
    float f1 = 1.f / fmaxf(sqrtf(ss1), 1e-12f);

    int gn0 = n0 + rowA;
    int gn1 = gn0 + 8;
    #pragma unroll
    for (int tl = 0; tl < 8; tl++) {
        int c0 = tl * 8 + 2 * t;
        if (gn0 < NN)
            *(float2*)&out[(size_t)gn0 * D + c0] = make_float2(acc[tl][0] * f0, acc[tl][1] * f0);
        if (gn1 < NN)
            *(float2*)&out[(size_t)gn1 * D + c0] = make_float2(acc[tl][2] * f1, acc[tl][3] * f1);
    }
}

#define SMEM_BYTES ((64 * IN_STRIDE + 2 * 128 * W_STRIDE + 64 * 3) * (int)sizeof(float))

extern "C" void kernel_launch(void* const* d_in, const int* in_sizes, int n_in,
                              void* d_out, int out_size) {
    const float* x   = (const float*)d_in[0];
    const int*   ei  = (const int*)d_in[1];
    const float* bmw = (const float*)d_in[2];
    const float* bmb = (const float*)d_in[3];
    const float* bsw = (const float*)d_in[4];
    const float* bsb = (const float*)d_in[5];
    const float* lc  = (const float*)d_in[6];
    float* out = (float*)d_out;

    void* hptr = nullptr;
    void* dptr = nullptr;
    cudaGetSymbolAddress(&hptr, g_h);
    cudaGetSymbolAddress(&dptr, g_deg);
    cudaMemsetAsync(hptr, 0, sizeof(float) * (size_t)NN * D);
    cudaMemsetAsync(dptr, 0, sizeof(float) * NN);

    unsigned total = (unsigned)NE * 16u;
    k_scatter<<<(total + 255u) / 256u + 1u, 256>>>((const float4*)x, ei, bmw, bmb, bsw, bsb, lc);

    cudaFuncSetAttribute(k_transform, cudaFuncAttributeMaxDynamicSharedMemorySize, SMEM_BYTES);
    k_transform<<<(NN + 63) / 64, 128, SMEM_BYTES>>>(x, out);
}